// round 2
// baseline (speedup 1.0000x reference)
#include <cuda_runtime.h>
#include <cstdint>

#define V_ 50257
#define D_ 512
#define E_ 128
#define S_ 400
#define B_ 16
#define T_ 60
#define R_ 960      // T_*B_
#define K3_ 1536    // 3*D_

// ---------------- device scratch (static allocations only) ----------------
static __device__ float g_emb[T_*B_*E_];
static __device__ float g_hbuf[2][B_*D_];
static __device__ float g_c[B_*D_];
static __device__ float g_hd[T_*B_*D_];
static __device__ float g_qe[R_*D_];
static __device__ float g_qd[R_*D_];
static __device__ float g_Ae[R_*S_];
static __device__ float g_ce[R_*D_];
static __device__ float g_cd[R_*D_];
static __device__ float g_cat[R_*K3_];
static __device__ float g_psw[R_];
static __device__ float g_Wout[(size_t)V_*K3_];   // 309 MB
static __device__ float g_denom[R_];
static __device__ float g_tlogit[R_];
static __device__ float g_loss;

__device__ __forceinline__ float sigm(float x){ return 1.f/(1.f+__expf(-x)); }

// ---------------- init: zero accumulators, copy h0/c0 ----------------
__global__ void k_init(const float* __restrict__ h0, const float* __restrict__ c0){
    int i = blockIdx.x*blockDim.x + threadIdx.x;
    if(i < B_*D_){ g_hbuf[0][i] = h0[i]; g_c[i] = c0[i]; }
    if(i < R_) g_denom[i] = 0.f;
    if(i == 0) g_loss = 0.f;
}

// ---------------- embedding gather ----------------
__global__ void k_embed(const int* __restrict__ tgt, const float* __restrict__ W_emb){
    int r = blockIdx.x, e = threadIdx.x;
    g_emb[r*E_ + e] = W_emb[(size_t)tgt[r]*E_ + e];
}

// ---------------- one LSTM step ----------------
// grid 128 blocks (each owns 4 d-values x 4 gates x 16 batch), block 256
__global__ void k_lstm(const float* __restrict__ W_ih, const float* __restrict__ W_hh,
                       const float* __restrict__ b_ih, const float* __restrict__ b_hh, int t){
    __shared__ float sx[16][129];
    __shared__ float sh[16][513];
    __shared__ float sg[4][4][16];
    int tid = threadIdx.x;
    const float* hin = g_hbuf[t & 1];
    for(int i=tid;i<B_*E_;i+=256){ int b=i/E_, e=i-b*E_; sx[b][e] = g_emb[(t*B_+b)*E_+e]; }
    for(int i=tid;i<B_*D_;i+=256){ int b=i/D_, d=i-b*D_; sh[b][d] = hin[i]; }
    __syncthreads();
    int b  = tid & 15;
    int j  = tid >> 4;
    int gate = j >> 2, dl = j & 3;
    int d0 = blockIdx.x * 4;
    int row = gate*D_ + d0 + dl;
    float acc = b_ih[row] + b_hh[row];
    const float4* wi = (const float4*)(W_ih + (size_t)row*E_);
    #pragma unroll 8
    for(int e4=0;e4<E_/4;e4++){
        float4 w = wi[e4]; int e=e4*4;
        acc += sx[b][e]*w.x + sx[b][e+1]*w.y + sx[b][e+2]*w.z + sx[b][e+3]*w.w;
    }
    const float4* wh = (const float4*)(W_hh + (size_t)row*D_);
    #pragma unroll 8
    for(int k4=0;k4<D_/4;k4++){
        float4 w = wh[k4]; int k=k4*4;
        acc += sh[b][k]*w.x + sh[b][k+1]*w.y + sh[b][k+2]*w.z + sh[b][k+3]*w.w;
    }
    sg[gate][dl][b] = acc;
    __syncthreads();
    if(tid < 64){
        int bb = tid & 15, dd = tid >> 4;
        int d = d0 + dd;
        float gi = sg[0][dd][bb], gf = sg[1][dd][bb], gg = sg[2][dd][bb], go = sg[3][dd][bb];
        float c = sigm(gf)*g_c[bb*D_+d] + sigm(gi)*tanhf(gg);
        float h = sigm(go)*tanhf(c);
        g_c[bb*D_+d] = c;
        g_hbuf[(t&1)^1][bb*D_+d] = h;
        g_hd[(t*B_+bb)*D_+d] = h;
    }
}

// ---------------- q = hd @ W_attn_{e,d}  (960x512)@(512x512) ----------------
// grid (60, 2), block 256; block = 16 rows, thread = 2 cols
__global__ void k_q(const float* __restrict__ W_e, const float* __restrict__ W_d){
    __shared__ float shd[16][513];
    int tid = threadIdx.x;
    int r0 = blockIdx.x * 16;
    for(int i=tid;i<16*D_;i+=256){ int ri=i>>9, d=i&511; shd[ri][d] = g_hd[(r0+ri)*D_+d]; }
    __syncthreads();
    const float* W = blockIdx.y ? W_d : W_e;
    float* out = blockIdx.y ? g_qd : g_qe;
    float acc0[16], acc1[16];
    #pragma unroll
    for(int i=0;i<16;i++){ acc0[i]=0.f; acc1[i]=0.f; }
    for(int d=0; d<D_; d++){
        float2 w = ((const float2*)(W + (size_t)d*D_))[tid];
        #pragma unroll
        for(int ri=0;ri<16;ri++){
            float h = shd[ri][d];
            acc0[ri] += h*w.x; acc1[ri] += h*w.y;
        }
    }
    int c0 = tid*2;
    #pragma unroll
    for(int ri=0;ri<16;ri++){
        out[(r0+ri)*D_ + c0]   = acc0[ri];
        out[(r0+ri)*D_ + c0+1] = acc1[ri];
    }
}

// ---------------- encoder attention (max-free softmax; exact) ----------------
// grid (4 t-chunks of 15, 16 b), block 512, dynamic smem
__global__ void k_enc_attn(const float* __restrict__ h_e){
    extern __shared__ float sm[];
    float* sq   = sm;              // 15*512
    float* she  = sq  + 15*512;    // 16*512
    float* ssc  = she + 16*512;    // 15*400  (exp'd scores)
    float* sw   = ssc + 15*400;    // 15*16
    float* sden = sw  + 240;       // 15
    int tid = threadIdx.x;
    int b = blockIdx.y, tc = blockIdx.x;
    int tbase = tc*15;
    for(int i=tid;i<15*512;i+=512){
        int ti=i>>9, d=i&511;
        sq[i] = g_qe[((tbase+ti)*B_+b)*D_+d];
    }
    float acc[15];
    #pragma unroll
    for(int i=0;i<15;i++) acc[i]=0.f;
    int d = tid;
    int wid = tid>>5, lane = tid&31;
    for(int sc0=0; sc0<S_; sc0+=16){
        __syncthreads();
        for(int i=tid;i<16*512;i+=512){
            int si=i>>9, dd=i&511;
            she[i] = h_e[((size_t)(sc0+si)*B_ + b)*D_ + dd];
        }
        __syncthreads();
        for(int p=wid*15; p<wid*15+15; p++){
            int ti = p>>4, si = p&15;
            float s = 0.f;
            #pragma unroll
            for(int dd=lane; dd<512; dd+=32) s += sq[ti*512+dd]*she[si*512+dd];
            #pragma unroll
            for(int o=16;o;o>>=1) s += __shfl_xor_sync(0xffffffffu, s, o);
            if(lane==0){
                float e = __expf(s);
                ssc[ti*400 + sc0 + si] = e;
                sw[ti*16 + si] = e;
            }
        }
        __syncthreads();
        #pragma unroll
        for(int si=0;si<16;si++){
            float hv = she[si*512 + d];
            #pragma unroll
            for(int ti=0;ti<15;ti++) acc[ti] += sw[ti*16+si]*hv;
        }
    }
    __syncthreads();
    if(tid < 15*32){
        int ti = tid>>5, l = tid&31;
        float s = 0.f;
        for(int sI=l; sI<S_; sI+=32) s += ssc[ti*400+sI];
        #pragma unroll
        for(int o=16;o;o>>=1) s += __shfl_xor_sync(0xffffffffu, s, o);
        if(l==0) sden[ti] = s;
    }
    __syncthreads();
    #pragma unroll
    for(int ti=0;ti<15;ti++)
        g_ce[((tbase+ti)*B_+b)*D_ + d] = acc[ti]/sden[ti];
    for(int i=tid;i<15*400;i+=512){
        int ti = i/400, sI = i - ti*400;
        g_Ae[((tbase+ti)*B_+b)*S_ + sI] = ssc[i]/sden[ti];
    }
}

// ---------------- decoder (causal) attention ----------------
__global__ void k_dec_attn(){
    __shared__ float sq[512];
    __shared__ float sw2[64];
    __shared__ float sden2;
    int r = blockIdx.x;
    int t = r>>4, b = r&15;
    int tid = threadIdx.x;
    for(int i=tid;i<512;i+=128) sq[i] = g_qd[r*D_+i];
    __syncthreads();
    int wid = tid>>5, lane = tid&31;
    for(int u=wid; u<=t; u+=4){
        const float* hr = g_hd + (u*B_+b)*D_;
        float s = 0.f;
        #pragma unroll
        for(int dd=lane; dd<512; dd+=32) s += sq[dd]*hr[dd];
        #pragma unroll
        for(int o=16;o;o>>=1) s += __shfl_xor_sync(0xffffffffu, s, o);
        if(lane==0) sw2[u] = __expf(s);
    }
    __syncthreads();
    if(tid < 32){
        float s = 0.f;
        for(int u=tid; u<=t; u+=32) s += sw2[u];
        #pragma unroll
        for(int o=16;o;o>>=1) s += __shfl_xor_sync(0xffffffffu, s, o);
        if(tid==0) sden2 = s;
    }
    __syncthreads();
    float inv = 1.0f/sden2;
    for(int dd=tid; dd<512; dd+=128){
        float a = 0.f;
        for(int u=0;u<=t;u++) a += sw2[u]*g_hd[(u*B_+b)*D_+dd];
        g_cd[r*D_+dd] = (t==0) ? 0.f : a*inv;
    }
}

// ---------------- cat = [hd|c_e|c_d]; p_switch ----------------
__global__ void k_cat(const float* __restrict__ W_u, const float* __restrict__ b_u){
    __shared__ float red[256];
    int r = blockIdx.x, tid = threadIdx.x;
    float part = 0.f;
    for(int k=tid;k<K3_;k+=256){
        float v;
        if(k < 512)       v = g_hd[r*D_ + k];
        else if(k < 1024) v = g_ce[r*D_ + k-512];
        else              v = g_cd[r*D_ + k-1024];
        g_cat[r*K3_ + k] = v;
        part += v*W_u[k];
    }
    red[tid] = part; __syncthreads();
    for(int o=128;o;o>>=1){ if(tid<o) red[tid]+=red[tid+o]; __syncthreads(); }
    if(tid==0) g_psw[r] = 1.f/(1.f + __expf(-(red[0] + b_u[0])));
}

// ---------------- W_out = tanh(W_emb @ W_proj) ----------------
// grid (ceil(V/64), 6), block 256; micro 8x8
__global__ void k_wout(const float* __restrict__ W_emb, const float* __restrict__ W_proj){
    __shared__ float sA[64][128];
    int tid = threadIdx.x;
    int v0 = blockIdx.x*64, c0 = blockIdx.y*256;
    for(int i=tid;i<64*128;i+=256){
        int rI=i>>7, k=i&127;
        int v = v0 + rI;
        sA[rI][k] = (v < V_) ? W_emb[(size_t)v*E_ + k] : 0.f;
    }
    __syncthreads();
    int lane = tid&31, warp = tid>>5;
    int ri0 = warp*8;
    int cA = c0 + lane*4;
    float acc[8][8];
    #pragma unroll
    for(int i=0;i<8;i++){
        #pragma unroll
        for(int jj=0;jj<8;jj++) acc[i][jj]=0.f;
    }
    for(int k=0;k<128;k++){
        float4 b0 = *(const float4*)(W_proj + (size_t)k*K3_ + cA);
        float4 b1 = *(const float4*)(W_proj + (size_t)k*K3_ + cA + 128);
        #pragma unroll
        for(int i=0;i<8;i++){
            float a = sA[ri0+i][k];
            acc[i][0]+=a*b0.x; acc[i][1]+=a*b0.y; acc[i][2]+=a*b0.z; acc[i][3]+=a*b0.w;
            acc[i][4]+=a*b1.x; acc[i][5]+=a*b1.y; acc[i][6]+=a*b1.z; acc[i][7]+=a*b1.w;
        }
    }
    #pragma unroll
    for(int i=0;i<8;i++){
        int v = v0 + ri0 + i;
        if(v < V_){
            float4 o0 = make_float4(tanhf(acc[i][0]),tanhf(acc[i][1]),tanhf(acc[i][2]),tanhf(acc[i][3]));
            float4 o1 = make_float4(tanhf(acc[i][4]),tanhf(acc[i][5]),tanhf(acc[i][6]),tanhf(acc[i][7]));
            *(float4*)(g_Wout + (size_t)v*K3_ + cA)       = o0;
            *(float4*)(g_Wout + (size_t)v*K3_ + cA + 128) = o1;
        }
    }
}

// ---------------- big GEMM + fused exp-row-sum (denominator) ----------------
// M=960, N=50257, K=1536; tile 128x128x16; grid (8, 393), block 256
__global__ void k_gemm(const float* __restrict__ b_out){
    __shared__ float sA[16][128];
    __shared__ float sB[16][128];
    __shared__ float sred[128][16];
    int tid = threadIdx.x;
    int m0 = blockIdx.x*128;
    int n0 = blockIdx.y*128;
    int tc = tid & 15, tr = tid >> 4;
    float acc[8][8];
    #pragma unroll
    for(int i=0;i<8;i++){
        #pragma unroll
        for(int jj=0;jj<8;jj++) acc[i][jj]=0.f;
    }
    for(int k0=0;k0<K3_;k0+=16){
        __syncthreads();
        #pragma unroll
        for(int l=0;l<2;l++){
            int f = tid + l*256;
            int m = f >> 2, kq = (f & 3)*4;
            float4 v = make_float4(0.f,0.f,0.f,0.f);
            int gm = m0 + m;
            if(gm < R_) v = *(const float4*)(g_cat + (size_t)gm*K3_ + k0 + kq);
            sA[kq+0][m]=v.x; sA[kq+1][m]=v.y; sA[kq+2][m]=v.z; sA[kq+3][m]=v.w;
        }
        #pragma unroll
        for(int l=0;l<2;l++){
            int f = tid + l*256;
            int n = f >> 2, kq = (f & 3)*4;
            float4 v = make_float4(0.f,0.f,0.f,0.f);
            int gn = n0 + n;
            if(gn < V_) v = *(const float4*)(g_Wout + (size_t)gn*K3_ + k0 + kq);
            sB[kq+0][n]=v.x; sB[kq+1][n]=v.y; sB[kq+2][n]=v.z; sB[kq+3][n]=v.w;
        }
        __syncthreads();
        #pragma unroll
        for(int k=0;k<16;k++){
            float4 a0 = *(const float4*)&sA[k][tr*8];
            float4 a1 = *(const float4*)&sA[k][tr*8+4];
            float a[8] = {a0.x,a0.y,a0.z,a0.w,a1.x,a1.y,a1.z,a1.w};
            float bb[8];
            #pragma unroll
            for(int i4=0;i4<4;i4++){
                float2 bv = *(const float2*)&sB[k][tc*2 + 32*i4];
                bb[2*i4] = bv.x; bb[2*i4+1] = bv.y;
            }
            #pragma unroll
            for(int i=0;i<8;i++){
                #pragma unroll
                for(int jj=0;jj<8;jj++) acc[i][jj] += a[i]*bb[jj];
            }
        }
    }
    __syncthreads();
    #pragma unroll
    for(int mi=0; mi<8; mi++){
        float s = 0.f;
        #pragma unroll
        for(int i4=0;i4<4;i4++){
            #pragma unroll
            for(int q=0;q<2;q++){
                int n = n0 + tc*2 + 32*i4 + q;
                if(n < V_) s += __expf(acc[mi][2*i4+q] + b_out[n]);
            }
        }
        sred[tr*8+mi][tc] = s;
    }
    __syncthreads();
    if(tid < 128){
        float s = 0.f;
        #pragma unroll
        for(int jj=0;jj<16;jj++) s += sred[tid][jj];
        int m = m0 + tid;
        if(m < R_) atomicAdd(&g_denom[m], s);
    }
}

// ---------------- exp(logit) at the target index ----------------
__global__ void k_targ(const int* __restrict__ tgt, const float* __restrict__ b_out){
    __shared__ float red[256];
    int r = blockIdx.x, tid = threadIdx.x;
    int v = tgt[r];
    const float* wr = g_Wout + (size_t)v*K3_;
    float part = 0.f;
    for(int k=tid;k<K3_;k+=256) part += g_cat[r*K3_+k]*wr[k];
    red[tid] = part; __syncthreads();
    for(int o=128;o;o>>=1){ if(tid<o) red[tid]+=red[tid+o]; __syncthreads(); }
    if(tid==0) g_tlogit[r] = __expf(red[0] + b_out[v]);
}

// ---------------- per-row loss + global sum ----------------
__global__ void k_loss(const int* __restrict__ tgt, const float* __restrict__ align){
    __shared__ float red[128];
    int r = blockIdx.x, tid = threadIdx.x;
    float part = 0.f;
    for(int s=tid;s<S_;s+=128) part += g_Ae[r*S_+s]*align[(size_t)r*S_+s];
    red[tid] = part; __syncthreads();
    for(int o=64;o;o>>=1){ if(tid<o) red[tid]+=red[tid+o]; __syncthreads(); }
    if(tid==0){
        int v = tgt[r];
        if(v != 0){
            float psw = g_psw[r];
            float tcopy = psw*red[0] + 1e-12f;
            float tgen  = (1.f - psw)*g_tlogit[r]/g_denom[r];
            atomicAdd(&g_loss, -logf(tgen + tcopy + 1e-12f));
        }
    }
}

__global__ void k_out(float* __restrict__ out){ out[0] = g_loss; }

// ---------------- launch ----------------
extern "C" void kernel_launch(void* const* d_in, const int* in_sizes, int n_in,
                              void* d_out, int out_size){
    const int*   tgt    = (const int*)  d_in[0];
    const float* align  = (const float*)d_in[2];
    const float* h_e    = (const float*)d_in[3];
    const float* h0     = (const float*)d_in[4];
    const float* c0     = (const float*)d_in[5];
    const float* W_emb  = (const float*)d_in[6];
    const float* W_ih   = (const float*)d_in[7];
    const float* W_hh   = (const float*)d_in[8];
    const float* b_ih   = (const float*)d_in[9];
    const float* b_hh   = (const float*)d_in[10];
    const float* W_ae   = (const float*)d_in[11];
    const float* W_ad   = (const float*)d_in[12];
    const float* W_proj = (const float*)d_in[13];
    const float* W_u    = (const float*)d_in[14];
    const float* b_u    = (const float*)d_in[15];
    const float* b_out  = (const float*)d_in[16];
    float* out = (float*)d_out;

    const int ENC_SMEM = (15*512 + 16*512 + 15*400 + 15*16 + 16)*4;  // ~88.5 KB
    cudaFuncSetAttribute(k_enc_attn, cudaFuncAttributeMaxDynamicSharedMemorySize, ENC_SMEM);

    k_init<<<32,256>>>(h0, c0);
    k_embed<<<R_, E_>>>(tgt, W_emb);
    k_wout<<<dim3((V_+63)/64, 6), 256>>>(W_emb, W_proj);
    for(int t=0;t<T_;t++)
        k_lstm<<<128,256>>>(W_ih, W_hh, b_ih, b_hh, t);
    k_q<<<dim3(60,2), 256>>>(W_ae, W_ad);
    k_enc_attn<<<dim3(4,16), 512, ENC_SMEM>>>(h_e);
    k_dec_attn<<<R_,128>>>();
    k_cat<<<R_,256>>>(W_u, b_u);
    k_gemm<<<dim3(8,393), 256>>>(b_out);
    k_targ<<<R_,256>>>(tgt, b_out);
    k_loss<<<R_,128>>>(tgt, align);
    k_out<<<1,1>>>(out);
}

// round 3
// speedup vs baseline: 3.3954x; 3.3954x over previous
#include <cuda_runtime.h>
#include <cuda_bf16.h>
#include <cstdint>

#define V_ 50257
#define D_ 512
#define E_ 128
#define S_ 400
#define B_ 16
#define T_ 60
#define R_ 960      // T_*B_
#define K3_ 1536    // 3*D_

// ---------------- device scratch ----------------
static __device__ float g_emb[T_*B_*E_];
static __device__ float g_hbuf[2][B_*D_];
static __device__ float g_c[B_*D_];
static __device__ float g_hd[T_*B_*D_];
static __device__ float g_xg[(size_t)T_*2048*16];     // precomputed x-projection + biases
static __device__ float g_qe[R_*D_];
static __device__ float g_qd[R_*D_];
static __device__ float g_Ae[R_*S_];
static __device__ float g_ce[R_*D_];
static __device__ float g_cd[R_*D_];
static __device__ __align__(16) __nv_bfloat16 g_catb[R_*K3_];
static __device__ float g_psw[R_];
static __device__ __align__(16) __nv_bfloat16 g_Woutb[(size_t)V_*K3_];   // 154 MB
static __device__ float g_denom[R_];
static __device__ float g_tlogit[R_];
static __device__ float g_loss;

__device__ __forceinline__ float sigm(float x){ return 1.f/(1.f+__expf(-x)); }
__device__ __forceinline__ uint32_t sptr(const void* p){ return (uint32_t)__cvta_generic_to_shared(p); }

__device__ __forceinline__ void ldsm_x4(uint32_t &r0, uint32_t &r1, uint32_t &r2, uint32_t &r3, uint32_t addr){
    asm volatile("ldmatrix.sync.aligned.m8n8.x4.shared.b16 {%0,%1,%2,%3}, [%4];"
                 : "=r"(r0),"=r"(r1),"=r"(r2),"=r"(r3) : "r"(addr));
}
__device__ __forceinline__ void ldsm_x4_t(uint32_t &r0, uint32_t &r1, uint32_t &r2, uint32_t &r3, uint32_t addr){
    asm volatile("ldmatrix.sync.aligned.m8n8.x4.trans.shared.b16 {%0,%1,%2,%3}, [%4];"
                 : "=r"(r0),"=r"(r1),"=r"(r2),"=r"(r3) : "r"(addr));
}
__device__ __forceinline__ void mma16816(float* c, const uint32_t* a, const uint32_t* b){
    asm volatile("mma.sync.aligned.m16n8k16.row.col.f32.bf16.bf16.f32 "
                 "{%0,%1,%2,%3},{%4,%5,%6,%7},{%8,%9},{%0,%1,%2,%3};"
                 : "+f"(c[0]),"+f"(c[1]),"+f"(c[2]),"+f"(c[3])
                 : "r"(a[0]),"r"(a[1]),"r"(a[2]),"r"(a[3]), "r"(b[0]),"r"(b[1]));
}

// ---------------- init ----------------
__global__ void k_init(const float* __restrict__ h0, const float* __restrict__ c0){
    int i = blockIdx.x*blockDim.x + threadIdx.x;
    if(i < B_*D_){ g_hbuf[0][i] = h0[i]; g_c[i] = c0[i]; }
    if(i < R_) g_denom[i] = 0.f;
    if(i == 0) g_loss = 0.f;
}

// ---------------- embedding gather ----------------
__global__ void k_embed(const int* __restrict__ tgt, const float* __restrict__ W_emb){
    int r = blockIdx.x, e = threadIdx.x;
    g_emb[r*E_ + e] = W_emb[(size_t)tgt[r]*E_ + e];
}

// ---------------- x-projection for all steps: xg[t][row][b] = W_ih[row].emb[t,b] + b_ih+b_hh ----------------
// grid (256, 60), block 256 (8 warps = 8 rows)
__global__ void k_xproj(const float* __restrict__ W_ih, const float* __restrict__ b_ih,
                        const float* __restrict__ b_hh){
    __shared__ float se[16*128];
    int tid = threadIdx.x, t = blockIdx.y;
    for(int i=tid;i<16*128;i+=256) se[i] = g_emb[t*2048 + i];
    __syncthreads();
    int wid = tid>>5, lane = tid&31;
    int row = blockIdx.x*8 + wid;
    float acc[16];
    #pragma unroll
    for(int b=0;b<16;b++) acc[b]=0.f;
    const float* wr = W_ih + (size_t)row*E_;
    #pragma unroll
    for(int kk=0;kk<4;kk++){
        float w = wr[kk*32+lane]; int k = kk*32+lane;
        #pragma unroll
        for(int b=0;b<16;b++) acc[b] += w*se[b*128+k];
    }
    #pragma unroll
    for(int b=0;b<16;b++){
        #pragma unroll
        for(int o=16;o;o>>=1) acc[b] += __shfl_xor_sync(0xffffffffu, acc[b], o);
    }
    if(lane==0){
        float bias = b_ih[row] + b_hh[row];
        float* out = g_xg + ((size_t)t*2048 + row)*16;
        #pragma unroll
        for(int b=0;b<16;b++) out[b] = acc[b] + bias;
    }
}

// ---------------- one LSTM step: h@W_hh^T + xg -> gates -> c,h ----------------
// grid 256 blocks (2 d-values each), block 256 (8 warps = 4 gates x 2 d)
__global__ void k_lstm(const float* __restrict__ W_hh, int t){
    __shared__ float sh[16*512];
    __shared__ float sg[8][16];
    int tid = threadIdx.x, wid = tid>>5, lane = tid&31;
    const float* hin = g_hbuf[t&1];
    for(int i=tid;i<16*512;i+=256) sh[i] = hin[i];
    __syncthreads();
    int gate = wid>>1, dd = wid&1;
    int d = blockIdx.x*2 + dd;
    int row = gate*D_ + d;
    float acc[16];
    #pragma unroll
    for(int b=0;b<16;b++) acc[b]=0.f;
    const float* wr = W_hh + (size_t)row*D_;
    #pragma unroll
    for(int kk=0;kk<16;kk++){
        float w = wr[kk*32+lane]; int k = kk*32+lane;
        #pragma unroll
        for(int b=0;b<16;b++) acc[b] += w*sh[b*512+k];
    }
    #pragma unroll
    for(int b=0;b<16;b++){
        #pragma unroll
        for(int o=16;o;o>>=1) acc[b] += __shfl_xor_sync(0xffffffffu, acc[b], o);
    }
    if(lane==0){
        const float* xg = g_xg + ((size_t)t*2048 + row)*16;
        #pragma unroll
        for(int b=0;b<16;b++) sg[wid][b] = acc[b] + xg[b];
    }
    __syncthreads();
    if(tid < 32){
        int b = tid&15, d2 = tid>>4;
        int dG = blockIdx.x*2 + d2;
        float gi = sg[0+d2][b], gf = sg[2+d2][b], gg = sg[4+d2][b], go = sg[6+d2][b];
        float c = sigm(gf)*g_c[b*D_+dG] + sigm(gi)*tanhf(gg);
        float h = sigm(go)*tanhf(c);
        g_c[b*D_+dG] = c;
        g_hbuf[(t&1)^1][b*D_+dG] = h;
        g_hd[(t*B_+b)*D_+dG] = h;
    }
}

// ---------------- q = hd @ W_attn_{e,d} ----------------
__global__ void k_q(const float* __restrict__ W_e, const float* __restrict__ W_d){
    __shared__ float shd[16][513];
    int tid = threadIdx.x;
    int r0 = blockIdx.x * 16;
    for(int i=tid;i<16*D_;i+=256){ int ri=i>>9, d=i&511; shd[ri][d] = g_hd[(r0+ri)*D_+d]; }
    __syncthreads();
    const float* W = blockIdx.y ? W_d : W_e;
    float* out = blockIdx.y ? g_qd : g_qe;
    float acc0[16], acc1[16];
    #pragma unroll
    for(int i=0;i<16;i++){ acc0[i]=0.f; acc1[i]=0.f; }
    for(int d=0; d<D_; d++){
        float2 w = ((const float2*)(W + (size_t)d*D_))[tid];
        #pragma unroll
        for(int ri=0;ri<16;ri++){
            float h = shd[ri][d];
            acc0[ri] += h*w.x; acc1[ri] += h*w.y;
        }
    }
    int c0 = tid*2;
    #pragma unroll
    for(int ri=0;ri<16;ri++){
        out[(r0+ri)*D_ + c0]   = acc0[ri];
        out[(r0+ri)*D_ + c0+1] = acc1[ri];
    }
}

// ---------------- encoder attention (max-free softmax; exact) ----------------
__global__ void k_enc_attn(const float* __restrict__ h_e){
    extern __shared__ float sm[];
    float* sq   = sm;              // 15*512
    float* she  = sq  + 15*512;    // 16*512
    float* ssc  = she + 16*512;    // 15*400
    float* sw   = ssc + 15*400;    // 15*16
    float* sden = sw  + 240;       // 15
    int tid = threadIdx.x;
    int b = blockIdx.y, tc = blockIdx.x;
    int tbase = tc*15;
    for(int i=tid;i<15*512;i+=512){
        int ti=i>>9, d=i&511;
        sq[i] = g_qe[((tbase+ti)*B_+b)*D_+d];
    }
    float acc[15];
    #pragma unroll
    for(int i=0;i<15;i++) acc[i]=0.f;
    int d = tid;
    int wid = tid>>5, lane = tid&31;
    for(int sc0=0; sc0<S_; sc0+=16){
        __syncthreads();
        for(int i=tid;i<16*512;i+=512){
            int si=i>>9, dd=i&511;
            she[i] = h_e[((size_t)(sc0+si)*B_ + b)*D_ + dd];
        }
        __syncthreads();
        for(int p=wid*15; p<wid*15+15; p++){
            int ti = p>>4, si = p&15;
            float s = 0.f;
            #pragma unroll
            for(int dd=lane; dd<512; dd+=32) s += sq[ti*512+dd]*she[si*512+dd];
            #pragma unroll
            for(int o=16;o;o>>=1) s += __shfl_xor_sync(0xffffffffu, s, o);
            if(lane==0){
                float e = __expf(s);
                ssc[ti*400 + sc0 + si] = e;
                sw[ti*16 + si] = e;
            }
        }
        __syncthreads();
        #pragma unroll
        for(int si=0;si<16;si++){
            float hv = she[si*512 + d];
            #pragma unroll
            for(int ti=0;ti<15;ti++) acc[ti] += sw[ti*16+si]*hv;
        }
    }
    __syncthreads();
    if(tid < 15*32){
        int ti = tid>>5, l = tid&31;
        float s = 0.f;
        for(int sI=l; sI<S_; sI+=32) s += ssc[ti*400+sI];
        #pragma unroll
        for(int o=16;o;o>>=1) s += __shfl_xor_sync(0xffffffffu, s, o);
        if(l==0) sden[ti] = s;
    }
    __syncthreads();
    #pragma unroll
    for(int ti=0;ti<15;ti++)
        g_ce[((tbase+ti)*B_+b)*D_ + d] = acc[ti]/sden[ti];
    for(int i=tid;i<15*400;i+=512){
        int ti = i/400, sI = i - ti*400;
        g_Ae[((tbase+ti)*B_+b)*S_ + sI] = ssc[i]/sden[ti];
    }
}

// ---------------- decoder (causal) attention ----------------
__global__ void k_dec_attn(){
    __shared__ float sq[512];
    __shared__ float sw2[64];
    __shared__ float sden2;
    int r = blockIdx.x;
    int t = r>>4, b = r&15;
    int tid = threadIdx.x;
    for(int i=tid;i<512;i+=128) sq[i] = g_qd[r*D_+i];
    __syncthreads();
    int wid = tid>>5, lane = tid&31;
    for(int u=wid; u<=t; u+=4){
        const float* hr = g_hd + (u*B_+b)*D_;
        float s = 0.f;
        #pragma unroll
        for(int dd=lane; dd<512; dd+=32) s += sq[dd]*hr[dd];
        #pragma unroll
        for(int o=16;o;o>>=1) s += __shfl_xor_sync(0xffffffffu, s, o);
        if(lane==0) sw2[u] = __expf(s);
    }
    __syncthreads();
    if(tid < 32){
        float s = 0.f;
        for(int u=tid; u<=t; u+=32) s += sw2[u];
        #pragma unroll
        for(int o=16;o;o>>=1) s += __shfl_xor_sync(0xffffffffu, s, o);
        if(tid==0) sden2 = s;
    }
    __syncthreads();
    float inv = 1.0f/sden2;
    for(int dd=tid; dd<512; dd+=128){
        float a = 0.f;
        for(int u=0;u<=t;u++) a += sw2[u]*g_hd[(u*B_+b)*D_+dd];
        g_cd[r*D_+dd] = (t==0) ? 0.f : a*inv;
    }
}

// ---------------- cat = [hd|c_e|c_d] (bf16); p_switch ----------------
__global__ void k_cat(const float* __restrict__ W_u, const float* __restrict__ b_u){
    __shared__ float red[256];
    int r = blockIdx.x, tid = threadIdx.x;
    float part = 0.f;
    for(int k=tid;k<K3_;k+=256){
        float v;
        if(k < 512)       v = g_hd[r*D_ + k];
        else if(k < 1024) v = g_ce[r*D_ + k-512];
        else              v = g_cd[r*D_ + k-1024];
        g_catb[r*K3_ + k] = __float2bfloat16(v);
        part += v*W_u[k];
    }
    red[tid] = part; __syncthreads();
    for(int o=128;o;o>>=1){ if(tid<o) red[tid]+=red[tid+o]; __syncthreads(); }
    if(tid==0) g_psw[r] = 1.f/(1.f + __expf(-(red[0] + b_u[0])));
}

// ---------------- W_out = tanh(W_emb @ W_proj) via bf16 mma, bf16 output ----------------
// M=V(50257), N=1536, K=128. grid (393, 12), block 256 (8 warps: 2m x 4n), tile 128x128
__global__ __launch_bounds__(256) void k_wout(const float* __restrict__ W_emb,
                                              const float* __restrict__ W_proj){
    extern __shared__ __nv_bfloat16 dyn[];
    __nv_bfloat16* sA = dyn;                 // [128][136]  (v, k)
    __nv_bfloat16* sB = dyn + 128*136;       // [128][136]  (k, n)
    const int LDA = 136;
    int tid = threadIdx.x, lane = tid&31, wid = tid>>5;
    int wm = wid>>2, wn = wid&3;
    int v0 = blockIdx.x*128, n0 = blockIdx.y*128;
    // load A (W_emb fp32 -> bf16): 128 rows x 32 float4
    #pragma unroll
    for(int i=0;i<16;i++){
        int idx = tid + i*256;
        int row = idx>>5, seg = idx&31;
        float4 f = make_float4(0.f,0.f,0.f,0.f);
        if(v0+row < V_) f = *(const float4*)(W_emb + (size_t)(v0+row)*E_ + seg*4);
        __nv_bfloat162 p0 = {__float2bfloat16(f.x), __float2bfloat16(f.y)};
        __nv_bfloat162 p1 = {__float2bfloat16(f.z), __float2bfloat16(f.w)};
        *(__nv_bfloat162*)(&sA[row*LDA + seg*4])   = p0;
        *(__nv_bfloat162*)(&sA[row*LDA + seg*4+2]) = p1;
        // load B (W_proj fp32 [k][n] -> bf16 smem [k][n])
        float4 g = *(const float4*)(W_proj + (size_t)row*K3_ + n0 + seg*4);
        __nv_bfloat162 q0 = {__float2bfloat16(g.x), __float2bfloat16(g.y)};
        __nv_bfloat162 q1 = {__float2bfloat16(g.z), __float2bfloat16(g.w)};
        *(__nv_bfloat162*)(&sB[row*LDA + seg*4])   = q0;
        *(__nv_bfloat162*)(&sB[row*LDA + seg*4+2]) = q1;
    }
    __syncthreads();
    float acc[4][4][4];
    #pragma unroll
    for(int mi=0;mi<4;mi++)
        #pragma unroll
        for(int ni=0;ni<4;ni++)
            #pragma unroll
            for(int q=0;q<4;q++) acc[mi][ni][q]=0.f;
    #pragma unroll
    for(int ks=0;ks<8;ks++){
        int kk = ks*16;
        uint32_t a[4][4], bfr[4][2];
        #pragma unroll
        for(int mi=0;mi<4;mi++){
            uint32_t addr = sptr(&sA[(wm*64 + mi*16 + (lane&15))*LDA + kk + (lane>>4)*8]);
            ldsm_x4(a[mi][0],a[mi][1],a[mi][2],a[mi][3], addr);
        }
        #pragma unroll
        for(int nb=0;nb<2;nb++){
            uint32_t addr = sptr(&sB[(kk + (lane&15))*LDA + wn*32 + nb*16 + (lane>>4)*8]);
            ldsm_x4_t(bfr[nb*2][0],bfr[nb*2][1],bfr[nb*2+1][0],bfr[nb*2+1][1], addr);
        }
        #pragma unroll
        for(int mi=0;mi<4;mi++)
            #pragma unroll
            for(int ni=0;ni<4;ni++)
                mma16816(acc[mi][ni], a[mi], bfr[ni]);
    }
    // epilogue: tanh -> bf16
    #pragma unroll
    for(int mi=0;mi<4;mi++){
        int v_lo = v0 + wm*64 + mi*16 + (lane>>2);
        #pragma unroll
        for(int ni=0;ni<4;ni++){
            int c = n0 + wn*32 + ni*8 + (lane&3)*2;
            if(v_lo < V_){
                __nv_bfloat162 o0 = {__float2bfloat16(tanhf(acc[mi][ni][0])),
                                     __float2bfloat16(tanhf(acc[mi][ni][1]))};
                *(__nv_bfloat162*)(g_Woutb + (size_t)v_lo*K3_ + c) = o0;
            }
            if(v_lo+8 < V_){
                __nv_bfloat162 o1 = {__float2bfloat16(tanhf(acc[mi][ni][2])),
                                     __float2bfloat16(tanhf(acc[mi][ni][3]))};
                *(__nv_bfloat162*)(g_Woutb + (size_t)(v_lo+8)*K3_ + c) = o1;
            }
        }
    }
}

// ---------------- big GEMM (bf16 mma) + fused exp-row-sum ----------------
// M=960, N=50257, K=1536; block tile 128x128, k-chunk 64; grid (8, 393), block 256
__global__ __launch_bounds__(256) void k_gemm(const float* __restrict__ b_out){
    __shared__ __nv_bfloat16 sA[128*72];   // [m][k] pad 8
    __shared__ __nv_bfloat16 sB[128*72];   // [n][k] pad 8
    __shared__ float sred[128][4];
    const int LDS = 72;
    int tid = threadIdx.x, lane = tid&31, wid = tid>>5;
    int wm = wid>>2, wn = wid&3;
    int m0 = blockIdx.x*128, n0 = blockIdx.y*128;
    float acc[4][4][4];
    #pragma unroll
    for(int mi=0;mi<4;mi++)
        #pragma unroll
        for(int ni=0;ni<4;ni++)
            #pragma unroll
            for(int q=0;q<4;q++) acc[mi][ni][q]=0.f;
    for(int k0=0;k0<K3_;k0+=64){
        __syncthreads();
        #pragma unroll
        for(int i=0;i<4;i++){
            int idx = tid + i*256;       // 0..1023
            int row = idx>>3, seg = idx&7;
            uint4 va = make_uint4(0,0,0,0);
            if(m0+row < R_) va = *(const uint4*)(g_catb + (size_t)(m0+row)*K3_ + k0 + seg*8);
            *(uint4*)(&sA[row*LDS + seg*8]) = va;
            uint4 vb = make_uint4(0,0,0,0);
            if(n0+row < V_) vb = *(const uint4*)(g_Woutb + (size_t)(n0+row)*K3_ + k0 + seg*8);
            *(uint4*)(&sB[row*LDS + seg*8]) = vb;
        }
        __syncthreads();
        #pragma unroll
        for(int ks=0;ks<4;ks++){
            int kk = ks*16;
            uint32_t a[4][4], bfr[4][2];
            #pragma unroll
            for(int mi=0;mi<4;mi++){
                uint32_t addr = sptr(&sA[(wm*64 + mi*16 + (lane&15))*LDS + kk + (lane>>4)*8]);
                ldsm_x4(a[mi][0],a[mi][1],a[mi][2],a[mi][3], addr);
            }
            #pragma unroll
            for(int nb=0;nb<2;nb++){
                uint32_t addr = sptr(&sB[(wn*32 + nb*16 + ((lane>>4)<<3) + (lane&7))*LDS
                                         + kk + ((lane>>3)&1)*8]);
                ldsm_x4(bfr[nb*2][0],bfr[nb*2][1],bfr[nb*2+1][0],bfr[nb*2+1][1], addr);
            }
            #pragma unroll
            for(int mi=0;mi<4;mi++)
                #pragma unroll
                for(int ni=0;ni<4;ni++)
                    mma16816(acc[mi][ni], a[mi], bfr[ni]);
        }
    }
    // epilogue: exp + per-row partial sums
    #pragma unroll
    for(int mi=0;mi<4;mi++){
        int ml = wm*64 + mi*16 + (lane>>2);
        int gm0 = m0 + ml, gm1 = gm0 + 8;
        float s0 = 0.f, s1 = 0.f;
        #pragma unroll
        for(int ni=0;ni<4;ni++){
            int gn = n0 + wn*32 + ni*8 + (lane&3)*2;
            if(gn < V_){
                float bo = b_out[gn];
                s0 += __expf(acc[mi][ni][0] + bo);
                s1 += __expf(acc[mi][ni][2] + bo);
            }
            if(gn+1 < V_){
                float bo = b_out[gn+1];
                s0 += __expf(acc[mi][ni][1] + bo);
                s1 += __expf(acc[mi][ni][3] + bo);
            }
        }
        if(gm0 >= R_) s0 = 0.f;
        if(gm1 >= R_) s1 = 0.f;
        s0 += __shfl_xor_sync(0xffffffffu, s0, 1); s0 += __shfl_xor_sync(0xffffffffu, s0, 2);
        s1 += __shfl_xor_sync(0xffffffffu, s1, 1); s1 += __shfl_xor_sync(0xffffffffu, s1, 2);
        if((lane&3)==0){
            sred[ml][wn]   = s0;
            sred[ml+8][wn] = s1;
        }
    }
    __syncthreads();
    if(tid < 128){
        int m = m0 + tid;
        if(m < R_){
            float s = sred[tid][0]+sred[tid][1]+sred[tid][2]+sred[tid][3];
            atomicAdd(&g_denom[m], s);
        }
    }
}

// ---------------- exp(logit) at the target index (bf16 dot, fp32 accum) ----------------
__global__ void k_targ(const int* __restrict__ tgt, const float* __restrict__ b_out){
    __shared__ float red[256];
    int r = blockIdx.x, tid = threadIdx.x;
    int v = tgt[r];
    const __nv_bfloat16* wr = g_Woutb + (size_t)v*K3_;
    const __nv_bfloat16* cr = g_catb + (size_t)r*K3_;
    float part = 0.f;
    for(int k=tid;k<K3_;k+=256) part += __bfloat162float(cr[k])*__bfloat162float(wr[k]);
    red[tid] = part; __syncthreads();
    for(int o=128;o;o>>=1){ if(tid<o) red[tid]+=red[tid+o]; __syncthreads(); }
    if(tid==0) g_tlogit[r] = __expf(red[0] + b_out[v]);
}

// ---------------- per-row loss + global sum ----------------
__global__ void k_loss(const int* __restrict__ tgt, const float* __restrict__ align){
    __shared__ float red[128];
    int r = blockIdx.x, tid = threadIdx.x;
    float part = 0.f;
    for(int s=tid;s<S_;s+=128) part += g_Ae[r*S_+s]*align[(size_t)r*S_+s];
    red[tid] = part; __syncthreads();
    for(int o=64;o;o>>=1){ if(tid<o) red[tid]+=red[tid+o]; __syncthreads(); }
    if(tid==0){
        int v = tgt[r];
        if(v != 0){
            float psw = g_psw[r];
            float tcopy = psw*red[0] + 1e-12f;
            float tgen  = (1.f - psw)*g_tlogit[r]/g_denom[r];
            atomicAdd(&g_loss, -logf(tgen + tcopy + 1e-12f));
        }
    }
}

__global__ void k_out(float* __restrict__ out){ out[0] = g_loss; }

// ---------------- launch ----------------
extern "C" void kernel_launch(void* const* d_in, const int* in_sizes, int n_in,
                              void* d_out, int out_size){
    const int*   tgt    = (const int*)  d_in[0];
    const float* align  = (const float*)d_in[2];
    const float* h_e    = (const float*)d_in[3];
    const float* h0     = (const float*)d_in[4];
    const float* c0     = (const float*)d_in[5];
    const float* W_emb  = (const float*)d_in[6];
    const float* W_ih   = (const float*)d_in[7];
    const float* W_hh   = (const float*)d_in[8];
    const float* b_ih   = (const float*)d_in[9];
    const float* b_hh   = (const float*)d_in[10];
    const float* W_ae   = (const float*)d_in[11];
    const float* W_ad   = (const float*)d_in[12];
    const float* W_proj = (const float*)d_in[13];
    const float* W_u    = (const float*)d_in[14];
    const float* b_u    = (const float*)d_in[15];
    const float* b_out  = (const float*)d_in[16];
    float* out = (float*)d_out;

    const int ENC_SMEM = (15*512 + 16*512 + 15*400 + 15*16 + 16)*4;  // ~88.5 KB
    cudaFuncSetAttribute(k_enc_attn, cudaFuncAttributeMaxDynamicSharedMemorySize, ENC_SMEM);
    const int WOUT_SMEM = 2*128*136*2;  // 69632 B
    cudaFuncSetAttribute(k_wout, cudaFuncAttributeMaxDynamicSharedMemorySize, WOUT_SMEM);

    k_init<<<32,256>>>(h0, c0);
    k_embed<<<R_, E_>>>(tgt, W_emb);
    k_xproj<<<dim3(256,60), 256>>>(W_ih, b_ih, b_hh);
    k_wout<<<dim3((V_+127)/128, 12), 256, WOUT_SMEM>>>(W_emb, W_proj);
    for(int t=0;t<T_;t++)
        k_lstm<<<256,256>>>(W_hh, t);
    k_q<<<dim3(60,2), 256>>>(W_ae, W_ad);
    k_enc_attn<<<dim3(4,16), 512, ENC_SMEM>>>(h_e);
    k_dec_attn<<<R_,128>>>();
    k_cat<<<R_,256>>>(W_u, b_u);
    k_gemm<<<dim3(8,393), 256>>>(b_out);
    k_targ<<<R_,256>>>(tgt, b_out);
    k_loss<<<R_,128>>>(tgt, align);
    k_out<<<1,1>>>(out);
}